// round 4
// baseline (speedup 1.0000x reference)
#include <cuda_runtime.h>
#include <cuda_bf16.h>

// ---------------------------------------------------------------------------
// GATModel: 2x (GEMM -> attention scores -> segment-softmax aggregate -> BN+ELU)
//           -> final GEMM + bias
// N=50000 nodes, E=500000 edges, F=256, H=4 heads, D=64, OUT=64
//
// edge_index dtype: the reference asks for int64 but JAX (x64 disabled)
// materializes int32. We runtime-detect the dtype on device and guard all
// data-derived indices so bad indices can never trap (err 717 in R1-R3).
// ---------------------------------------------------------------------------

#define NMAX 50000
#define EMAX 500000

// Scratch (device globals; referenced directly by symbol inside kernels)
__device__ float g_buf1[NMAX * 256];    // GEMM output / hfeat
__device__ float g_buf2[NMAX * 256];    // aggregate output / next-layer input
__device__ float g_ssrc[NMAX * 4];
__device__ float g_sdst[NMAX * 4];
__device__ int   g_counts[NMAX];
__device__ int   g_rowptr[NMAX + 1];
__device__ int   g_cursor[NMAX];
__device__ int   g_csrc[EMAX];
__device__ int   g_is64;                // 1 if edge_index is int64, else int32

// ---------------- edge_index dtype detection ----------------
__global__ void detect_dtype(const void* __restrict__ ei, int N) {
    // Interpreting as int64: real int64 indices are all in [0, N).
    // int32 data reinterpreted as int64 has a (almost surely) nonzero high
    // word -> value >= 2^32. Sample 16 values.
    const long long* p = (const long long*)ei;
    int ok = 1;
    for (int i = 0; i < 16; i++) {
        long long v = p[i];
        if (v < 0 || v >= (long long)N) ok = 0;
    }
    g_is64 = ok;
}

__device__ __forceinline__ int load_idx(const void* ei, long long pos) {
    if (g_is64) {
        long long v = ((const long long*)ei)[pos];
        return (int)v;
    }
    return ((const int*)ei)[pos];
}

// ---------------- CSR build ----------------
__global__ void zero_counts(int N) {
    int i = blockIdx.x * blockDim.x + threadIdx.x;
    if (i < N) g_counts[i] = 0;
}

__global__ void hist_kernel(const void* __restrict__ ei, int E, int N) {
    int e = blockIdx.x * blockDim.x + threadIdx.x;
    if (e < E) {
        int d = load_idx(ei, (long long)E + e);
        if (d >= 0 && d < N) atomicAdd(&g_counts[d], 1);
    }
}

__global__ void scan_kernel(int N) {
    __shared__ int sums[1024];
    int tid = threadIdx.x;
    int per = (N + 1023) / 1024;
    int base = tid * per;
    int s = 0;
    for (int i = 0; i < per; i++) {
        int idx = base + i;
        if (idx < N) s += g_counts[idx];
    }
    sums[tid] = s;
    __syncthreads();
    for (int off = 1; off < 1024; off <<= 1) {
        int v = 0;
        if (tid >= off) v = sums[tid - off];
        __syncthreads();
        if (tid >= off) sums[tid] += v;
        __syncthreads();
    }
    int run = (tid == 0) ? 0 : sums[tid - 1];
    for (int i = 0; i < per; i++) {
        int idx = base + i;
        if (idx < N) {
            g_rowptr[idx] = run;
            g_cursor[idx] = run;
            run += g_counts[idx];
        }
    }
    if (tid == 1023) g_rowptr[N] = sums[1023];
}

__global__ void scatter_kernel(const void* __restrict__ ei, int E, int N) {
    int e = blockIdx.x * blockDim.x + threadIdx.x;
    if (e < E) {
        int d = load_idx(ei, (long long)E + e);
        int s = load_idx(ei, e);
        if (d >= 0 && d < N && s >= 0 && s < N) {
            int pos = atomicAdd(&g_cursor[d], 1);
            if (pos >= 0 && pos < E) g_csrc[pos] = s;
        }
    }
}

// ---------------- GEMM: C[M,Nout] = A[M,256] * B[Nout,256]^T (+ bias) --------
// BM=128, BN=64, BK=16, 256 threads (16x16), TM=8, TN=4, scalar FFMA.
__global__ void __launch_bounds__(256)
gemm_tn(const float* __restrict__ Aext, int useBuf2,
        const float* __restrict__ B,
        const float* __restrict__ bias,
        float* __restrict__ Cext, int toExt,
        int M, int Nout) {
    const int BM = 128, BN = 64, BK = 16, TM = 8;
    __shared__ float As[BK][BM + 4];
    __shared__ float Bs[BK][BN + 4];

    const float* A = useBuf2 ? (const float*)g_buf2 : Aext;
    float* C = toExt ? Cext : (float*)g_buf1;

    int tid = threadIdx.x;
    int tx = tid & 15;
    int ty = tid >> 4;
    int row0 = blockIdx.x * BM;
    int col0 = blockIdx.y * BN;

    float acc[TM][4];
#pragma unroll
    for (int i = 0; i < TM; i++)
#pragma unroll
        for (int j = 0; j < 4; j++) acc[i][j] = 0.f;

    const int lr = tid >> 2;          // 0..63
    const int lk = (tid & 3) * 4;     // 0,4,8,12

    for (int kt = 0; kt < 256; kt += BK) {
#pragma unroll
        for (int h = 0; h < 2; h++) {
            int r = lr + h * 64;
            int grow = row0 + r;
            float4 v = make_float4(0.f, 0.f, 0.f, 0.f);
            if (grow < M) v = *(const float4*)&A[(size_t)grow * 256 + kt + lk];
            As[lk + 0][r] = v.x;
            As[lk + 1][r] = v.y;
            As[lk + 2][r] = v.z;
            As[lk + 3][r] = v.w;
        }
        {
            int r = lr;
            float4 v = *(const float4*)&B[(size_t)(col0 + r) * 256 + kt + lk];
            Bs[lk + 0][r] = v.x;
            Bs[lk + 1][r] = v.y;
            Bs[lk + 2][r] = v.z;
            Bs[lk + 3][r] = v.w;
        }
        __syncthreads();
#pragma unroll
        for (int k = 0; k < BK; k++) {
            float a[TM], b[4];
            *(float4*)&a[0] = *(const float4*)&As[k][ty * TM];
            *(float4*)&a[4] = *(const float4*)&As[k][ty * TM + 4];
            *(float4*)&b[0] = *(const float4*)&Bs[k][tx * 4];
#pragma unroll
            for (int i = 0; i < TM; i++) {
#pragma unroll
                for (int j = 0; j < 4; j++)
                    acc[i][j] = fmaf(a[i], b[j], acc[i][j]);
            }
        }
        __syncthreads();
    }

    int c = col0 + tx * 4;
    float bx = 0.f, by = 0.f, bz = 0.f, bw = 0.f;
    if (bias) {
        bx = bias[c]; by = bias[c + 1]; bz = bias[c + 2]; bw = bias[c + 3];
    }
#pragma unroll
    for (int i = 0; i < TM; i++) {
        int r = row0 + ty * TM + i;
        if (r < M) {
            float4 o = make_float4(acc[i][0] + bx, acc[i][1] + by,
                                   acc[i][2] + bz, acc[i][3] + bw);
            *(float4*)&C[(size_t)r * Nout + c] = o;
        }
    }
}

// ---------------- attention scores: s[n][h] = <h[n,h,:], a[h,:]> ------------
__global__ void __launch_bounds__(128)
scores_kernel(const float* __restrict__ a_src, const float* __restrict__ a_dst) {
    int n = blockIdx.x;
    int w = threadIdx.x >> 5;
    int lane = threadIdx.x & 31;
    const float* hf = g_buf1;
    float h0 = hf[(size_t)n * 256 + w * 64 + lane];
    float h1 = hf[(size_t)n * 256 + w * 64 + 32 + lane];
    float vs = h0 * a_src[w * 64 + lane] + h1 * a_src[w * 64 + 32 + lane];
    float vd = h0 * a_dst[w * 64 + lane] + h1 * a_dst[w * 64 + 32 + lane];
#pragma unroll
    for (int o = 16; o; o >>= 1) {
        vs += __shfl_xor_sync(~0u, vs, o);
        vd += __shfl_xor_sync(~0u, vd, o);
    }
    if (!lane) {
        g_ssrc[n * 4 + w] = vs;
        g_sdst[n * 4 + w] = vd;
    }
}

// ---------------- GAT aggregate (segment softmax, gather form) + BN + ELU ---
// One 128-thread block per dst node; warp w owns head w; thread owns 2 channels.
__global__ void __launch_bounds__(128)
gat_agg(const float* __restrict__ gamma, const float* __restrict__ beta,
        const float* __restrict__ mean, const float* __restrict__ var) {
    int n = blockIdx.x;
    int tid = threadIdx.x;
    int head = tid >> 5;
    int lane = tid & 31;
    int beg = g_rowptr[n];
    int end = g_rowptr[n + 1];
    float sd = g_sdst[n * 4 + head];
    const float* hfeat = g_buf1;

    // per-head max (implicit 0 from torch index_reduce include_self)
    float m = 0.f;
    for (int i = beg + lane; i < end; i += 32) {
        int s = g_csrc[i];
        float e = g_ssrc[s * 4 + head] + sd;
        e = (e >= 0.f) ? e : 0.2f * e;
        m = fmaxf(m, e);
    }
#pragma unroll
    for (int o = 16; o; o >>= 1) m = fmaxf(m, __shfl_xor_sync(~0u, m, o));

    // weighted accumulation
    float acc0 = 0.f, acc1 = 0.f, ws = 0.f;
    int c = tid * 2;
    for (int i = beg; i < end; i++) {
        int s = g_csrc[i];
        float e = g_ssrc[s * 4 + head] + sd;
        e = (e >= 0.f) ? e : 0.2f * e;
        float wgt = __expf(e - m);
        ws += wgt;
        float2 hv = *(const float2*)&hfeat[(size_t)s * 256 + c];
        acc0 = fmaf(wgt, hv.x, acc0);
        acc1 = fmaf(wgt, hv.y, acc1);
    }
    float inv = 1.f / fmaxf(ws, 1e-9f);
    float o0 = acc0 * inv;
    float o1 = acc1 * inv;

    // BN (eval) + ELU
    o0 = (o0 - mean[c]) * rsqrtf(var[c] + 1e-5f) * gamma[c] + beta[c];
    o1 = (o1 - mean[c + 1]) * rsqrtf(var[c + 1] + 1e-5f) * gamma[c + 1] + beta[c + 1];
    o0 = (o0 > 0.f) ? o0 : expm1f(o0);
    o1 = (o1 > 0.f) ? o1 : expm1f(o1);
    *(float2*)&g_buf2[(size_t)n * 256 + c] = make_float2(o0, o1);
}

// ---------------------------------------------------------------------------
extern "C" void kernel_launch(void* const* d_in, const int* in_sizes, int n_in,
                              void* d_out, int out_size) {
    const float* x   = (const float*)d_in[0];
    const void*  ei  = d_in[1];                 // int32 or int64, detected on device
    const float* W1  = (const float*)d_in[2];
    const float* as1 = (const float*)d_in[3];
    const float* ad1 = (const float*)d_in[4];
    const float* g1  = (const float*)d_in[5];
    const float* b1  = (const float*)d_in[6];
    const float* m1  = (const float*)d_in[7];
    const float* v1  = (const float*)d_in[8];
    const float* W2  = (const float*)d_in[9];
    const float* as2 = (const float*)d_in[10];
    const float* ad2 = (const float*)d_in[11];
    const float* g2  = (const float*)d_in[12];
    const float* b2  = (const float*)d_in[13];
    const float* m2  = (const float*)d_in[14];
    const float* v2  = (const float*)d_in[15];
    const float* Wc  = (const float*)d_in[16];
    const float* bc  = (const float*)d_in[17];
    float* out = (float*)d_out;

    int N = in_sizes[0] / 256;
    int E = in_sizes[1] / 2;

    // --- detect edge_index dtype, then build CSR by dst ---
    detect_dtype<<<1, 1>>>(ei, N);
    zero_counts<<<(N + 255) / 256, 256>>>(N);
    hist_kernel<<<(E + 255) / 256, 256>>>(ei, E, N);
    scan_kernel<<<1, 1024>>>(N);
    scatter_kernel<<<(E + 255) / 256, 256>>>(ei, E, N);

    dim3 gemm_grid((N + 127) / 128, 4);
    dim3 gemm_grid_c((N + 127) / 128, 1);

    // --- layer 1 ---  (A = x, C = g_buf1)
    gemm_tn<<<gemm_grid, 256>>>(x, 0, W1, nullptr, nullptr, 0, N, 256);
    scores_kernel<<<N, 128>>>(as1, ad1);
    gat_agg<<<N, 128>>>(g1, b1, m1, v1);

    // --- layer 2 ---  (A = g_buf2, C = g_buf1)
    gemm_tn<<<gemm_grid, 256>>>(nullptr, 1, W2, nullptr, nullptr, 0, N, 256);
    scores_kernel<<<N, 128>>>(as2, ad2);
    gat_agg<<<N, 128>>>(g2, b2, m2, v2);

    // --- classifier ---  (A = g_buf2, C = out)
    gemm_tn<<<gemm_grid_c, 256>>>(nullptr, 1, Wc, bc, out, 1, N, 64);
}